// round 10
// baseline (speedup 1.0000x reference)
#include <cuda_runtime.h>
#include <math.h>

// Problem constants (fixed by the dataset)
#define N_NODES   170000
#define N_EDGES   1200000
#define D_FEAT    128
#define N_CLASSES 40
#define D4        (D_FEAT / 4)    // 32 float4 per x row
#define C4        (N_CLASSES / 4) // 10 float4 per z row (160 B)

#define SCAN_B  1024
#define SCAN_NB ((N_NODES + SCAN_B - 1) / SCAN_B)   // 167

// ---- scratch (device globals; no allocations allowed) ----
__device__ float4 g_zs0[(size_t)N_NODES * C4];   // 27.2 MB  (dinv-scaled projected feats)
__device__ float4 g_zs1[(size_t)N_NODES * C4];   // 27.2 MB  (dinv-scaled hop-1 output)
__device__ int    g_deg[N_NODES];
__device__ int    g_off[N_NODES + 1];
__device__ int    g_bsum[SCAN_NB];
__device__ int    g_srcs[N_EDGES];
__device__ float  g_dinv[N_NODES];
__device__ int    g_is64;   // 1 if edge_index is int64, 0 if int32

__device__ __forceinline__ int clampN(int v) {
    return ((unsigned)v < (unsigned)N_NODES) ? v : 0;
}

// ---- 1. zero degree + (block 0, warp 0) probe edge dtype ----
// int64 edge data has all-zero high (odd int32) words.
__global__ void k_zero(const int* __restrict__ ei32) {
    if (blockIdx.x == 0 && threadIdx.x < 32) {
        int lane = threadIdx.x;
        int w0 = ei32[2 * lane + 1];
        int w1 = ei32[2 * (lane + 32) + 1];
        unsigned nz = __ballot_sync(0xffffffffu, (w0 | w1) != 0);
        if (lane == 0) g_is64 = (nz == 0u) ? 1 : 0;
    }
    int i = blockIdx.x * blockDim.x + threadIdx.x;
    if (i < N_NODES) g_deg[i] = 0;
}

// ---- 2. in-degree histogram over dst: 2 edges per thread, vector loads ----
__global__ void k_count(const void* __restrict__ ei) {
    int t = blockIdx.x * blockDim.x + threadIdx.x;
    if (t >= N_EDGES / 2) return;
    int d0, d1;
    if (g_is64) {
        longlong2 d2 = ((const longlong2*)ei)[(N_EDGES / 2) + t];
        d0 = clampN((int)d2.x); d1 = clampN((int)d2.y);
    } else {
        int2 d2 = ((const int2*)ei)[(N_EDGES / 2) + t];
        d0 = clampN(d2.x); d1 = clampN(d2.y);
    }
    atomicAdd(&g_deg[d0], 1);
    atomicAdd(&g_deg[d1], 1);
}

// ---- 3-5. exclusive scan of g_deg -> g_off (3-phase); scan1 also emits dinv ----
__global__ void k_scan1() {
    __shared__ int sh[SCAN_B];
    int i = blockIdx.x * SCAN_B + threadIdx.x;
    int v = (i < N_NODES) ? g_deg[i] : 0;
    if (i < N_NODES) g_dinv[i] = rsqrtf((float)(v + 1));   // fused dinv
    sh[threadIdx.x] = v;
    __syncthreads();
    for (int d = 1; d < SCAN_B; d <<= 1) {
        int t = (threadIdx.x >= d) ? sh[threadIdx.x - d] : 0;
        __syncthreads();
        sh[threadIdx.x] += t;
        __syncthreads();
    }
    if (i < N_NODES) g_off[i] = sh[threadIdx.x] - v;   // exclusive
    if (threadIdx.x == SCAN_B - 1) g_bsum[blockIdx.x] = sh[SCAN_B - 1];
}

__global__ void k_scan2() {
    __shared__ int sh[256];
    int tid = threadIdx.x;
    int v = (tid < SCAN_NB) ? g_bsum[tid] : 0;
    sh[tid] = v;
    __syncthreads();
    for (int d = 1; d < 256; d <<= 1) {
        int t = (tid >= d) ? sh[tid - d] : 0;
        __syncthreads();
        sh[tid] += t;
        __syncthreads();
    }
    if (tid < SCAN_NB) g_bsum[tid] = sh[tid] - v;      // exclusive block offsets
}

__global__ void k_scan3() {
    int i = blockIdx.x * SCAN_B + threadIdx.x;
    if (i < N_NODES) g_off[i] += g_bsum[blockIdx.x];
}

// ---- 6. project X(128) -> zs0(40) = dinv[n] * (X[n] . W^T), thread per node ----
// Computed in two 20-class halves to cap live registers => no spill.
__global__ void __launch_bounds__(256) k_project(const float4* __restrict__ x4,
                                                 const float4* __restrict__ W4) {
    __shared__ float4 sW[N_CLASSES][D4];   // 20 KB
    for (int i = threadIdx.x; i < N_CLASSES * D4; i += blockDim.x)
        (&sW[0][0])[i] = W4[i];
    __syncthreads();

    int node = blockIdx.x * blockDim.x + threadIdx.x;
    if (node >= N_NODES) return;

    const float4* h = x4 + (size_t)node * D4;
    float di = g_dinv[node];
    float4* z = g_zs0 + (size_t)node * C4;

    #pragma unroll 1
    for (int half = 0; half < 2; half++) {
        float acc[20];
        #pragma unroll
        for (int c = 0; c < 20; c++) acc[c] = 0.f;

        #pragma unroll 2
        for (int k = 0; k < D4; k++) {
            float4 hv = h[k];                 // half 2: L1 hit (just touched)
            #pragma unroll
            for (int c = 0; c < 20; c++) {
                float4 w = sW[half * 20 + c][k];   // broadcast
                acc[c] = fmaf(hv.x, w.x, acc[c]);
                acc[c] = fmaf(hv.y, w.y, acc[c]);
                acc[c] = fmaf(hv.z, w.z, acc[c]);
                acc[c] = fmaf(hv.w, w.w, acc[c]);
            }
        }

        #pragma unroll
        for (int c = 0; c < 5; c++) {
            float4 v;
            v.x = di * acc[4 * c + 0];
            v.y = di * acc[4 * c + 1];
            v.z = di * acc[4 * c + 2];
            v.w = di * acc[4 * c + 3];
            z[half * 5 + c] = v;
        }
    }
}

// ---- 7. scatter edges into CSR-by-dst: atomic-append on g_off directly ----
// 2 edges per thread, vector loads. Afterwards g_off[d] == END offset of d
// (shifted CSR: beg(d) = (d==0) ? 0 : g_off[d-1]).
__global__ void k_scatter(const void* __restrict__ ei) {
    int t = blockIdx.x * blockDim.x + threadIdx.x;
    if (t >= N_EDGES / 2) return;
    int s0, s1, d0, d1;
    if (g_is64) {
        longlong2 s2 = ((const longlong2*)ei)[t];
        longlong2 d2 = ((const longlong2*)ei)[(N_EDGES / 2) + t];
        s0 = clampN((int)s2.x); s1 = clampN((int)s2.y);
        d0 = clampN((int)d2.x); d1 = clampN((int)d2.y);
    } else {
        int2 s2 = ((const int2*)ei)[t];
        int2 d2 = ((const int2*)ei)[(N_EDGES / 2) + t];
        s0 = clampN(s2.x); s1 = clampN(s2.y);
        d0 = clampN(d2.x); d1 = clampN(d2.y);
    }
    g_srcs[atomicAdd(&g_off[d0], 1)] = s0;
    g_srcs[atomicAdd(&g_off[d1], 1)] = s1;
}

// ---- 8. propagation hop: TWO nodes per warp, float4 gathers, 4x MLP ----
// Half-warp (16 lanes) per node; lanes 0..9 of each half hold the 10 float4
// of the 160B row. Shifted CSR: beg = off[node-1] (0 for node 0), end = off[node].
// t[i] = sum_{s->i} zin[s] + zin[i] (rows pre-scaled by dinv).
// pass0:  zs1[i] = dinv[i]^2 * t[i]
// pass1:  logits = dinv[i] * t[i] + b; out = log_softmax(logits)
__global__ void __launch_bounds__(256) k_hop(int pass,
                                             const float4* __restrict__ b4,
                                             float4*       __restrict__ out4) {
    const float4* zin = (pass == 0) ? (const float4*)g_zs0 : (const float4*)g_zs1;

    int warp = (blockIdx.x * blockDim.x + threadIdx.x) >> 5;
    int lane = threadIdx.x & 31;
    int half = lane >> 4;          // 0 or 1
    int hl   = lane & 15;          // lane within half
    int node = warp * 2 + half;    // N_NODES even; grid sized exactly
    bool act = hl < C4;            // lanes 0..9 active

    int beg = 0, end = 0;
    if (act) {
        beg = (node == 0) ? 0 : g_off[node - 1];
        end = g_off[node];
    }

    // self term
    float4 a = make_float4(0.f, 0.f, 0.f, 0.f);
    if (act) a = zin[(size_t)node * C4 + hl];

    // gather-sum over in-edges, 4x unrolled => 4 independent gathers in flight
    int p = beg;
    for (; p + 3 < end; p += 4) {
        int s0 = g_srcs[p];
        int s1 = g_srcs[p + 1];
        int s2 = g_srcs[p + 2];
        int s3 = g_srcs[p + 3];
        float4 u0 = zin[(size_t)s0 * C4 + hl];
        float4 u1 = zin[(size_t)s1 * C4 + hl];
        float4 u2 = zin[(size_t)s2 * C4 + hl];
        float4 u3 = zin[(size_t)s3 * C4 + hl];
        a.x += (u0.x + u1.x) + (u2.x + u3.x);
        a.y += (u0.y + u1.y) + (u2.y + u3.y);
        a.z += (u0.z + u1.z) + (u2.z + u3.z);
        a.w += (u0.w + u1.w) + (u2.w + u3.w);
    }
    for (; p < end; p++) {
        float4 u = zin[(size_t)g_srcs[p] * C4 + hl];
        a.x += u.x; a.y += u.y; a.z += u.z; a.w += u.w;
    }

    float di = act ? g_dinv[node] : 0.f;
    if (pass == 0) {
        if (act) {
            float di2 = di * di;
            float4 o;
            o.x = di2 * a.x; o.y = di2 * a.y; o.z = di2 * a.z; o.w = di2 * a.w;
            g_zs1[(size_t)node * C4 + hl] = o;
        }
    } else {
        float4 l = make_float4(-INFINITY, -INFINITY, -INFINITY, -INFINITY);
        if (act) {
            float4 bb = b4[hl];
            l.x = fmaf(di, a.x, bb.x);
            l.y = fmaf(di, a.y, bb.y);
            l.z = fmaf(di, a.z, bb.z);
            l.w = fmaf(di, a.w, bb.w);
        }

        // component-wise max/sum reduced across the 16-lane half
        float m = fmaxf(fmaxf(l.x, l.y), fmaxf(l.z, l.w));
        #pragma unroll
        for (int d = 8; d >= 1; d >>= 1)
            m = fmaxf(m, __shfl_xor_sync(0xffffffffu, m, d));

        float s = __expf(l.x - m) + __expf(l.y - m) +
                  __expf(l.z - m) + __expf(l.w - m);   // inactive: 4*exp(-inf)=0
        #pragma unroll
        for (int d = 8; d >= 1; d >>= 1)
            s += __shfl_xor_sync(0xffffffffu, s, d);

        float lse = m + logf(s);
        if (act) {
            float4 o;
            o.x = l.x - lse; o.y = l.y - lse; o.z = l.z - lse; o.w = l.w - lse;
            out4[(size_t)node * C4 + hl] = o;
        }
    }
}

extern "C" void kernel_launch(void* const* d_in, const int* in_sizes, int n_in,
                              void* d_out, int out_size) {
    const float4* x4  = (const float4*)d_in[0];
    const void*   ei  = d_in[1];
    const float4* W4  = (const float4*)d_in[2];
    const float4* b4  = (const float4*)d_in[3];
    float4*       out4 = (float4*)d_out;
    (void)in_sizes; (void)n_in; (void)out_size;

    const int TB = 256;
    int nblk_nodes = (N_NODES + TB - 1) / TB;
    int nblk_epair = (N_EDGES / 2 + TB - 1) / TB;

    k_zero<<<nblk_nodes, TB>>>((const int*)ei);   // + dtype probe
    k_count<<<nblk_epair, TB>>>(ei);
    k_scan1<<<SCAN_NB, SCAN_B>>>();               // + dinv
    k_scan2<<<1, 256>>>();
    k_scan3<<<SCAN_NB, SCAN_B>>>();
    k_project<<<nblk_nodes, TB>>>(x4, W4);
    k_scatter<<<nblk_epair, TB>>>(ei);

    // 2 hops: two nodes per warp => N_NODES/2 warps
    int nblk_hop = (N_NODES / 2) * 32 / TB;       // 10625 blocks exactly
    k_hop<<<nblk_hop, TB>>>(0, b4, out4);
    k_hop<<<nblk_hop, TB>>>(1, b4, out4);
}

// round 11
// speedup vs baseline: 1.0476x; 1.0476x over previous
#include <cuda_runtime.h>
#include <math.h>

// Problem constants (fixed by the dataset)
#define N_NODES   170000
#define N_EDGES   1200000
#define D_FEAT    128
#define N_CLASSES 40
#define D4        (D_FEAT / 4)    // 32 float4 per x row
#define C4        (N_CLASSES / 4) // 10 float4 per z row (160 B)

#define SCAN_B  1024
#define SCAN_NB ((N_NODES + SCAN_B - 1) / SCAN_B)   // 167

// ---- scratch (device globals; no allocations allowed) ----
__device__ float4 g_zs0[(size_t)N_NODES * C4];   // 27.2 MB  (dinv-scaled projected feats)
__device__ float4 g_zs1[(size_t)N_NODES * C4];   // 27.2 MB  (dinv-scaled hop-1 output)
__device__ int    g_deg[N_NODES];
__device__ int    g_off[N_NODES + 1];
__device__ int    g_bsum[SCAN_NB];
__device__ int    g_srcs[N_EDGES];
__device__ float  g_dinv[N_NODES];
__device__ int    g_is64;   // 1 if edge_index is int64, 0 if int32

__device__ __forceinline__ int clampN(int v) {
    return ((unsigned)v < (unsigned)N_NODES) ? v : 0;
}

// ---- 1. zero degree + (block 0, warp 0) probe edge dtype ----
// int64 edge data has all-zero high (odd int32) words.
__global__ void k_zero(const int* __restrict__ ei32) {
    if (blockIdx.x == 0 && threadIdx.x < 32) {
        int lane = threadIdx.x;
        int w0 = ei32[2 * lane + 1];
        int w1 = ei32[2 * (lane + 32) + 1];
        unsigned nz = __ballot_sync(0xffffffffu, (w0 | w1) != 0);
        if (lane == 0) g_is64 = (nz == 0u) ? 1 : 0;
    }
    int i = blockIdx.x * blockDim.x + threadIdx.x;
    if (i < N_NODES) g_deg[i] = 0;
}

// ---- 2. in-degree histogram over dst: 2 edges per thread, vector loads ----
__global__ void k_count(const void* __restrict__ ei) {
    int t = blockIdx.x * blockDim.x + threadIdx.x;
    if (t >= N_EDGES / 2) return;
    int d0, d1;
    if (g_is64) {
        longlong2 d2 = ((const longlong2*)ei)[(N_EDGES / 2) + t];
        d0 = clampN((int)d2.x); d1 = clampN((int)d2.y);
    } else {
        int2 d2 = ((const int2*)ei)[(N_EDGES / 2) + t];
        d0 = clampN(d2.x); d1 = clampN(d2.y);
    }
    atomicAdd(&g_deg[d0], 1);
    atomicAdd(&g_deg[d1], 1);
}

// ---- 3-5. exclusive scan of g_deg -> g_off (3-phase); scan1 also emits dinv ----
__global__ void k_scan1() {
    __shared__ int sh[SCAN_B];
    int i = blockIdx.x * SCAN_B + threadIdx.x;
    int v = (i < N_NODES) ? g_deg[i] : 0;
    if (i < N_NODES) g_dinv[i] = rsqrtf((float)(v + 1));   // fused dinv
    sh[threadIdx.x] = v;
    __syncthreads();
    for (int d = 1; d < SCAN_B; d <<= 1) {
        int t = (threadIdx.x >= d) ? sh[threadIdx.x - d] : 0;
        __syncthreads();
        sh[threadIdx.x] += t;
        __syncthreads();
    }
    if (i < N_NODES) g_off[i] = sh[threadIdx.x] - v;   // exclusive
    if (threadIdx.x == SCAN_B - 1) g_bsum[blockIdx.x] = sh[SCAN_B - 1];
}

__global__ void k_scan2() {
    __shared__ int sh[256];
    int tid = threadIdx.x;
    int v = (tid < SCAN_NB) ? g_bsum[tid] : 0;
    sh[tid] = v;
    __syncthreads();
    for (int d = 1; d < 256; d <<= 1) {
        int t = (tid >= d) ? sh[tid - d] : 0;
        __syncthreads();
        sh[tid] += t;
        __syncthreads();
    }
    if (tid < SCAN_NB) g_bsum[tid] = sh[tid] - v;      // exclusive block offsets
}

__global__ void k_scan3() {
    int i = blockIdx.x * SCAN_B + threadIdx.x;
    if (i < N_NODES) g_off[i] += g_bsum[blockIdx.x];
}

// ---- 6. project X(128) -> zs0(40) = dinv[n] * (X[n] . W^T), thread per node ----
// Computed in two 20-class halves to cap live registers => no spill.
__global__ void __launch_bounds__(256) k_project(const float4* __restrict__ x4,
                                                 const float4* __restrict__ W4) {
    __shared__ float4 sW[N_CLASSES][D4];   // 20 KB
    for (int i = threadIdx.x; i < N_CLASSES * D4; i += blockDim.x)
        (&sW[0][0])[i] = W4[i];
    __syncthreads();

    int node = blockIdx.x * blockDim.x + threadIdx.x;
    if (node >= N_NODES) return;

    const float4* h = x4 + (size_t)node * D4;
    float di = g_dinv[node];
    float4* z = g_zs0 + (size_t)node * C4;

    #pragma unroll 1
    for (int half = 0; half < 2; half++) {
        float acc[20];
        #pragma unroll
        for (int c = 0; c < 20; c++) acc[c] = 0.f;

        #pragma unroll 2
        for (int k = 0; k < D4; k++) {
            float4 hv = h[k];                 // half 2: L1 hit (just touched)
            #pragma unroll
            for (int c = 0; c < 20; c++) {
                float4 w = sW[half * 20 + c][k];   // broadcast
                acc[c] = fmaf(hv.x, w.x, acc[c]);
                acc[c] = fmaf(hv.y, w.y, acc[c]);
                acc[c] = fmaf(hv.z, w.z, acc[c]);
                acc[c] = fmaf(hv.w, w.w, acc[c]);
            }
        }

        #pragma unroll
        for (int c = 0; c < 5; c++) {
            float4 v;
            v.x = di * acc[4 * c + 0];
            v.y = di * acc[4 * c + 1];
            v.z = di * acc[4 * c + 2];
            v.w = di * acc[4 * c + 3];
            z[half * 5 + c] = v;
        }
    }
}

// ---- 7. scatter edges into CSR-by-dst: atomic-append on g_off directly ----
// 2 edges per thread, vector loads. Afterwards g_off[d] == END offset of d
// (shifted CSR: beg(d) = (d==0) ? 0 : g_off[d-1]).
__global__ void k_scatter(const void* __restrict__ ei) {
    int t = blockIdx.x * blockDim.x + threadIdx.x;
    if (t >= N_EDGES / 2) return;
    int s0, s1, d0, d1;
    if (g_is64) {
        longlong2 s2 = ((const longlong2*)ei)[t];
        longlong2 d2 = ((const longlong2*)ei)[(N_EDGES / 2) + t];
        s0 = clampN((int)s2.x); s1 = clampN((int)s2.y);
        d0 = clampN((int)d2.x); d1 = clampN((int)d2.y);
    } else {
        int2 s2 = ((const int2*)ei)[t];
        int2 d2 = ((const int2*)ei)[(N_EDGES / 2) + t];
        s0 = clampN(s2.x); s1 = clampN(s2.y);
        d0 = clampN(d2.x); d1 = clampN(d2.y);
    }
    g_srcs[atomicAdd(&g_off[d0], 1)] = s0;
    g_srcs[atomicAdd(&g_off[d1], 1)] = s1;
}

// ---- 8. propagation hop: TWO nodes per warp, float4 gathers, 2x MLP ----
// Half-warp (16 lanes) per node; lanes 0..9 of each half hold the 10 float4
// of the 160B row. Shifted CSR: beg = off[node-1] (0 for node 0), end = off[node].
// t[i] = sum_{s->i} zin[s] + zin[i] (rows pre-scaled by dinv).
// pass0:  zs1[i] = dinv[i]^2 * t[i]
// pass1:  logits = dinv[i] * t[i] + b; out = log_softmax(logits)
__global__ void __launch_bounds__(256) k_hop(int pass,
                                             const float4* __restrict__ b4,
                                             float4*       __restrict__ out4) {
    const float4* zin = (pass == 0) ? (const float4*)g_zs0 : (const float4*)g_zs1;

    int warp = (blockIdx.x * blockDim.x + threadIdx.x) >> 5;
    int lane = threadIdx.x & 31;
    int half = lane >> 4;          // 0 or 1
    int hl   = lane & 15;          // lane within half
    int node = warp * 2 + half;    // N_NODES even; grid sized exactly
    bool act = hl < C4;            // lanes 0..9 active

    int beg = 0, end = 0;
    if (act) {
        beg = (node == 0) ? 0 : g_off[node - 1];
        end = g_off[node];
    }

    // self term
    float4 a = make_float4(0.f, 0.f, 0.f, 0.f);
    if (act) a = zin[(size_t)node * C4 + hl];

    // gather-sum over in-edges, 2x unrolled for MLP
    int p = beg;
    for (; p + 1 < end; p += 2) {
        int s0 = g_srcs[p];
        int s1 = g_srcs[p + 1];
        float4 u = zin[(size_t)s0 * C4 + hl];
        float4 v = zin[(size_t)s1 * C4 + hl];
        a.x += u.x + v.x;
        a.y += u.y + v.y;
        a.z += u.z + v.z;
        a.w += u.w + v.w;
    }
    if (p < end) {
        float4 u = zin[(size_t)g_srcs[p] * C4 + hl];
        a.x += u.x; a.y += u.y; a.z += u.z; a.w += u.w;
    }

    float di = act ? g_dinv[node] : 0.f;
    if (pass == 0) {
        if (act) {
            float di2 = di * di;
            float4 o;
            o.x = di2 * a.x; o.y = di2 * a.y; o.z = di2 * a.z; o.w = di2 * a.w;
            g_zs1[(size_t)node * C4 + hl] = o;
        }
    } else {
        float4 l = make_float4(-INFINITY, -INFINITY, -INFINITY, -INFINITY);
        if (act) {
            float4 bb = b4[hl];
            l.x = fmaf(di, a.x, bb.x);
            l.y = fmaf(di, a.y, bb.y);
            l.z = fmaf(di, a.z, bb.z);
            l.w = fmaf(di, a.w, bb.w);
        }

        // component-wise max/sum reduced across the 16-lane half
        float m = fmaxf(fmaxf(l.x, l.y), fmaxf(l.z, l.w));
        #pragma unroll
        for (int d = 8; d >= 1; d >>= 1)
            m = fmaxf(m, __shfl_xor_sync(0xffffffffu, m, d));

        float s = __expf(l.x - m) + __expf(l.y - m) +
                  __expf(l.z - m) + __expf(l.w - m);   // inactive: 4*exp(-inf)=0
        #pragma unroll
        for (int d = 8; d >= 1; d >>= 1)
            s += __shfl_xor_sync(0xffffffffu, s, d);

        float lse = m + logf(s);
        if (act) {
            float4 o;
            o.x = l.x - lse; o.y = l.y - lse; o.z = l.z - lse; o.w = l.w - lse;
            out4[(size_t)node * C4 + hl] = o;
        }
    }
}

extern "C" void kernel_launch(void* const* d_in, const int* in_sizes, int n_in,
                              void* d_out, int out_size) {
    const float4* x4  = (const float4*)d_in[0];
    const void*   ei  = d_in[1];
    const float4* W4  = (const float4*)d_in[2];
    const float4* b4  = (const float4*)d_in[3];
    float4*       out4 = (float4*)d_out;
    (void)in_sizes; (void)n_in; (void)out_size;

    const int TB = 256;
    int nblk_nodes = (N_NODES + TB - 1) / TB;
    int nblk_epair = (N_EDGES / 2 + TB - 1) / TB;

    k_zero<<<nblk_nodes, TB>>>((const int*)ei);   // + dtype probe
    k_count<<<nblk_epair, TB>>>(ei);
    k_scan1<<<SCAN_NB, SCAN_B>>>();               // + dinv
    k_scan2<<<1, 256>>>();
    k_scan3<<<SCAN_NB, SCAN_B>>>();
    k_project<<<nblk_nodes, TB>>>(x4, W4);
    k_scatter<<<nblk_epair, TB>>>(ei);

    // 2 hops: two nodes per warp => N_NODES/2 warps
    int nblk_hop = (N_NODES / 2) * 32 / TB;       // 10625 blocks exactly
    k_hop<<<nblk_hop, TB>>>(0, b4, out4);
    k_hop<<<nblk_hop, TB>>>(1, b4, out4);
}

// round 12
// speedup vs baseline: 1.1210x; 1.0701x over previous
#include <cuda_runtime.h>
#include <math.h>

// Problem constants (fixed by the dataset)
#define N_NODES   170000
#define N_EDGES   1200000
#define D_FEAT    128
#define N_CLASSES 40
#define D4        (D_FEAT / 4)    // 32 float4 per x row
#define C4        (N_CLASSES / 4) // 10 float4 per z row (160 B)

#define SCAN_B  1024
#define SCAN_NB ((N_NODES + SCAN_B - 1) / SCAN_B)   // 167

// ---- scratch (device globals; no allocations allowed) ----
__device__ float4 g_zs0[(size_t)N_NODES * C4];   // 27.2 MB  (dinv-scaled projected feats)
__device__ float4 g_zs1[(size_t)N_NODES * C4];   // 27.2 MB  (dinv-scaled hop-1 output)
__device__ int    g_deg[N_NODES];
__device__ int    g_off[N_NODES + 1];
__device__ unsigned long long g_state[SCAN_NB];  // lookback: (flag<<32)|sum
__device__ int    g_srcs[N_EDGES];
__device__ float  g_dinv[N_NODES];
__device__ int    g_is64;   // 1 if edge_index is int64, 0 if int32

__device__ __forceinline__ int clampN(int v) {
    return ((unsigned)v < (unsigned)N_NODES) ? v : 0;
}

#define FMA_F32X2(acc, a, b) \
    asm("fma.rn.f32x2 %0, %1, %2, %3;" : "=l"(acc) : "l"(a), "l"(b), "l"(acc))
#define PACK_F32X2(out, lo, hi) \
    asm("mov.b64 %0, {%1, %2};" : "=l"(out) : "f"(lo), "f"(hi))

// ---- 1. zero degree + lookback state + (block 0, warp 0) probe edge dtype ----
__global__ void k_zero(const int* __restrict__ ei32) {
    if (blockIdx.x == 0 && threadIdx.x < 32) {
        int lane = threadIdx.x;
        int w0 = ei32[2 * lane + 1];
        int w1 = ei32[2 * (lane + 32) + 1];
        unsigned nz = __ballot_sync(0xffffffffu, (w0 | w1) != 0);
        if (lane == 0) g_is64 = (nz == 0u) ? 1 : 0;
    }
    int i = blockIdx.x * blockDim.x + threadIdx.x;
    if (i < N_NODES) g_deg[i] = 0;
    if (i < SCAN_NB) g_state[i] = 0ull;
}

// ---- 2. in-degree histogram over dst: 2 edges per thread, vector loads ----
__global__ void k_count(const void* __restrict__ ei) {
    int t = blockIdx.x * blockDim.x + threadIdx.x;
    if (t >= N_EDGES / 2) return;
    int d0, d1;
    if (g_is64) {
        longlong2 d2 = ((const longlong2*)ei)[(N_EDGES / 2) + t];
        d0 = clampN((int)d2.x); d1 = clampN((int)d2.y);
    } else {
        int2 d2 = ((const int2*)ei)[(N_EDGES / 2) + t];
        d0 = clampN(d2.x); d1 = clampN(d2.y);
    }
    atomicAdd(&g_deg[d0], 1);
    atomicAdd(&g_deg[d1], 1);
}

// ---- 3. single-kernel exclusive scan (decoupled lookback) + dinv ----
// All SCAN_NB=167 blocks are chip-resident concurrently => spin-wait is safe.
__global__ void __launch_bounds__(SCAN_B) k_scan() {
    __shared__ int sh[SCAN_B];
    __shared__ unsigned sbase;
    int bid = blockIdx.x;
    int tid = threadIdx.x;
    int i = bid * SCAN_B + tid;

    int v = (i < N_NODES) ? g_deg[i] : 0;
    if (i < N_NODES) g_dinv[i] = rsqrtf((float)(v + 1));   // fused dinv

    sh[tid] = v;
    __syncthreads();
    for (int d = 1; d < SCAN_B; d <<= 1) {
        int t = (tid >= d) ? sh[tid - d] : 0;
        __syncthreads();
        sh[tid] += t;
        __syncthreads();
    }
    int incl = sh[tid];
    int total = sh[SCAN_B - 1];

    // publish aggregate (block 0 publishes its prefix directly)
    if (tid == 0) {
        unsigned long long pk = ((bid == 0) ? (2ull << 32) : (1ull << 32))
                              | (unsigned long long)(unsigned)total;
        atomicExch(&g_state[bid], pk);
        if (bid == 0) sbase = 0u;
    }

    // warp 0: parallel lookback (32 predecessors per round)
    if (tid < 32 && bid > 0) {
        int lane = tid;
        unsigned excl = 0;
        int j = bid - 1;
        while (true) {
            int idx = j - lane;
            unsigned long long pk;
            if (idx >= 0) {
                do { pk = atomicAdd(&g_state[idx], 0ull); } while ((pk >> 32) == 0ull);
            } else {
                pk = (2ull << 32);   // virtual prefix 0 before block 0
            }
            unsigned flag = (unsigned)(pk >> 32);
            unsigned val  = (unsigned)pk;
            unsigned pm = __ballot_sync(0xffffffffu, flag == 2u);
            unsigned contrib;
            if (pm) {
                int fp = __ffs(pm) - 1;          // closest prefix (lane fp)
                contrib = (lane <= fp) ? val : 0; // aggregates before it + the prefix
            } else {
                contrib = val;                    // all aggregates; keep walking
            }
            #pragma unroll
            for (int d = 16; d >= 1; d >>= 1)
                contrib += __shfl_xor_sync(0xffffffffu, contrib, d);
            excl += contrib;
            if (pm) break;
            j -= 32;
        }
        if (lane == 0) {
            sbase = excl;
            atomicExch(&g_state[bid], (2ull << 32) | (unsigned long long)(excl + (unsigned)total));
        }
    }
    __syncthreads();

    if (i < N_NODES) g_off[i] = (int)sbase + (incl - v);   // exclusive
}

// ---- 4. project X(128) -> zs0(40) = dinv[n] * (X[n].W^T), packed f32x2 FMA ----
// Weights staged in smem pair-transposed: sWf[(d*40)+c] = W[c][d], so one
// LDS.128 (as ulonglong2) yields 2 adjacent class-pairs for component d.
__global__ void __launch_bounds__(256) k_project(const float4* __restrict__ x4,
                                                 const float*  __restrict__ Wf) {
    __shared__ float sWf[D_FEAT * N_CLASSES];   // 20 KB, [d][c]
    for (int i = threadIdx.x; i < D_FEAT * N_CLASSES; i += blockDim.x) {
        int d = i / N_CLASSES, c = i % N_CLASSES;
        sWf[i] = Wf[c * D_FEAT + d];
    }
    __syncthreads();

    int node = blockIdx.x * blockDim.x + threadIdx.x;
    if (node >= N_NODES) return;

    unsigned long long acc[20];
    #pragma unroll
    for (int p = 0; p < 20; p++) acc[p] = 0ull;

    const float4* h = x4 + (size_t)node * D4;
    #pragma unroll 2
    for (int k = 0; k < D4; k++) {
        float4 hv = h[k];
        float hvp[4] = {hv.x, hv.y, hv.z, hv.w};
        #pragma unroll
        for (int comp = 0; comp < 4; comp++) {
            unsigned long long a2;
            PACK_F32X2(a2, hvp[comp], hvp[comp]);
            const ulonglong2* wrow =
                (const ulonglong2*)&sWf[(k * 4 + comp) * N_CLASSES];
            #pragma unroll
            for (int pp = 0; pp < 10; pp++) {
                ulonglong2 wv = wrow[pp];        // classes 4pp..4pp+3 of comp
                FMA_F32X2(acc[2 * pp],     a2, wv.x);
                FMA_F32X2(acc[2 * pp + 1], a2, wv.y);
            }
        }
    }

    float di = g_dinv[node];
    float4* z = g_zs0 + (size_t)node * C4;
    #pragma unroll
    for (int q = 0; q < 10; q++) {
        float4 o;
        o.x = di * __uint_as_float((unsigned)acc[2 * q]);
        o.y = di * __uint_as_float((unsigned)(acc[2 * q] >> 32));
        o.z = di * __uint_as_float((unsigned)acc[2 * q + 1]);
        o.w = di * __uint_as_float((unsigned)(acc[2 * q + 1] >> 32));
        z[q] = o;
    }
}

// ---- 5. scatter edges into CSR-by-dst: atomic-append on g_off directly ----
// Afterwards g_off[d] == END offset of d (shifted CSR: beg(d) = off[d-1], 0 for d=0).
__global__ void k_scatter(const void* __restrict__ ei) {
    int t = blockIdx.x * blockDim.x + threadIdx.x;
    if (t >= N_EDGES / 2) return;
    int s0, s1, d0, d1;
    if (g_is64) {
        longlong2 s2 = ((const longlong2*)ei)[t];
        longlong2 d2 = ((const longlong2*)ei)[(N_EDGES / 2) + t];
        s0 = clampN((int)s2.x); s1 = clampN((int)s2.y);
        d0 = clampN((int)d2.x); d1 = clampN((int)d2.y);
    } else {
        int2 s2 = ((const int2*)ei)[t];
        int2 d2 = ((const int2*)ei)[(N_EDGES / 2) + t];
        s0 = clampN(s2.x); s1 = clampN(s2.y);
        d0 = clampN(d2.x); d1 = clampN(d2.y);
    }
    g_srcs[atomicAdd(&g_off[d0], 1)] = s0;
    g_srcs[atomicAdd(&g_off[d1], 1)] = s1;
}

// ---- 6. propagation hop: TWO nodes per warp, float4 gathers, 2x MLP ----
// Half-warp (16 lanes) per node; lanes 0..9 hold the 10 float4 of the 160B row.
// Shifted CSR: beg = off[node-1] (0 for node 0), end = off[node].
// pass0:  zs1[i] = dinv[i]^2 * (sum zs0[s] + zs0[i])
// pass1:  logits = dinv[i] * (sum zs1[s] + zs1[i]) + b; out = log_softmax
__global__ void __launch_bounds__(256) k_hop(int pass,
                                             const float4* __restrict__ b4,
                                             float4*       __restrict__ out4) {
    const float4* zin = (pass == 0) ? (const float4*)g_zs0 : (const float4*)g_zs1;

    int warp = (blockIdx.x * blockDim.x + threadIdx.x) >> 5;
    int lane = threadIdx.x & 31;
    int half = lane >> 4;          // 0 or 1
    int hl   = lane & 15;          // lane within half
    int node = warp * 2 + half;    // N_NODES even; grid sized exactly
    bool act = hl < C4;            // lanes 0..9 active

    int beg = 0, end = 0;
    if (act) {
        beg = (node == 0) ? 0 : g_off[node - 1];
        end = g_off[node];
    }

    // self term
    float4 a = make_float4(0.f, 0.f, 0.f, 0.f);
    if (act) a = zin[(size_t)node * C4 + hl];

    // gather-sum over in-edges, 2x unrolled for MLP
    int p = beg;
    for (; p + 1 < end; p += 2) {
        int s0 = g_srcs[p];
        int s1 = g_srcs[p + 1];
        float4 u = zin[(size_t)s0 * C4 + hl];
        float4 v = zin[(size_t)s1 * C4 + hl];
        a.x += u.x + v.x;
        a.y += u.y + v.y;
        a.z += u.z + v.z;
        a.w += u.w + v.w;
    }
    if (p < end) {
        float4 u = zin[(size_t)g_srcs[p] * C4 + hl];
        a.x += u.x; a.y += u.y; a.z += u.z; a.w += u.w;
    }

    float di = act ? g_dinv[node] : 0.f;
    if (pass == 0) {
        if (act) {
            float di2 = di * di;
            float4 o;
            o.x = di2 * a.x; o.y = di2 * a.y; o.z = di2 * a.z; o.w = di2 * a.w;
            g_zs1[(size_t)node * C4 + hl] = o;
        }
    } else {
        float4 l = make_float4(-INFINITY, -INFINITY, -INFINITY, -INFINITY);
        if (act) {
            float4 bb = b4[hl];
            l.x = fmaf(di, a.x, bb.x);
            l.y = fmaf(di, a.y, bb.y);
            l.z = fmaf(di, a.z, bb.z);
            l.w = fmaf(di, a.w, bb.w);
        }

        float m = fmaxf(fmaxf(l.x, l.y), fmaxf(l.z, l.w));
        #pragma unroll
        for (int d = 8; d >= 1; d >>= 1)
            m = fmaxf(m, __shfl_xor_sync(0xffffffffu, m, d));

        float s = __expf(l.x - m) + __expf(l.y - m) +
                  __expf(l.z - m) + __expf(l.w - m);   // inactive: 4*exp(-inf)=0
        #pragma unroll
        for (int d = 8; d >= 1; d >>= 1)
            s += __shfl_xor_sync(0xffffffffu, s, d);

        float lse = m + logf(s);
        if (act) {
            float4 o;
            o.x = l.x - lse; o.y = l.y - lse; o.z = l.z - lse; o.w = l.w - lse;
            out4[(size_t)node * C4 + hl] = o;
        }
    }
}

extern "C" void kernel_launch(void* const* d_in, const int* in_sizes, int n_in,
                              void* d_out, int out_size) {
    const float4* x4  = (const float4*)d_in[0];
    const void*   ei  = d_in[1];
    const float*  Wf  = (const float*)d_in[2];
    const float4* b4  = (const float4*)d_in[3];
    float4*       out4 = (float4*)d_out;
    (void)in_sizes; (void)n_in; (void)out_size;

    const int TB = 256;
    int nblk_nodes = (N_NODES + TB - 1) / TB;
    int nblk_epair = (N_EDGES / 2 + TB - 1) / TB;

    k_zero<<<nblk_nodes, TB>>>((const int*)ei);   // + dtype probe + state reset
    k_count<<<nblk_epair, TB>>>(ei);
    k_scan<<<SCAN_NB, SCAN_B>>>();                // single-kernel scan + dinv
    k_project<<<nblk_nodes, TB>>>(x4, Wf);
    k_scatter<<<nblk_epair, TB>>>(ei);

    // 2 hops: two nodes per warp => N_NODES/2 warps
    int nblk_hop = (N_NODES / 2) * 32 / TB;       // 10625 blocks exactly
    k_hop<<<nblk_hop, TB>>>(0, b4, out4);
    k_hop<<<nblk_hop, TB>>>(1, b4, out4);
}

// round 13
// speedup vs baseline: 1.1989x; 1.0695x over previous
#include <cuda_runtime.h>
#include <math.h>

// Problem constants (fixed by the dataset)
#define N_NODES   170000
#define N_EDGES   1200000
#define D_FEAT    128
#define N_CLASSES 40
#define D4        (D_FEAT / 4)    // 32 float4 per x row
#define C4        (N_CLASSES / 4) // 10 float4 per z row (160 B)
#define NHALF     (N_NODES / 2)   // 85000

#define SCAN_B  1024
#define SCAN_NB ((N_NODES + SCAN_B - 1) / SCAN_B)   // 167

// ---- scratch (device globals; no allocations allowed) ----
__device__ float4 g_zs0[(size_t)N_NODES * C4];   // 27.2 MB  (dinv-scaled projected feats)
__device__ float4 g_zs1[(size_t)N_NODES * C4];   // 27.2 MB  (dinv-scaled hop-1 output)
__device__ int    g_deg[N_NODES];
__device__ int    g_off[N_NODES + 1];
__device__ unsigned long long g_state[SCAN_NB];  // lookback: (flag<<32)|sum
__device__ int    g_srcs[N_EDGES];
__device__ float  g_dinv[N_NODES];
__device__ int    g_is64;   // 1 if edge_index is int64, 0 if int32

__device__ __forceinline__ int clampN(int v) {
    return ((unsigned)v < (unsigned)N_NODES) ? v : 0;
}

#define FMA_F32X2(acc, a, b) \
    asm("fma.rn.f32x2 %0, %1, %2, %3;" : "=l"(acc) : "l"(a), "l"(b), "l"(acc))
#define PACK_F32X2(out, lo, hi) \
    asm("mov.b64 %0, {%1, %2};" : "=l"(out) : "f"(lo), "f"(hi))

// ---- 1. zero degree + lookback state + (block 0, warp 0) probe edge dtype ----
__global__ void k_zero(const int* __restrict__ ei32) {
    if (blockIdx.x == 0 && threadIdx.x < 32) {
        int lane = threadIdx.x;
        int w0 = ei32[2 * lane + 1];
        int w1 = ei32[2 * (lane + 32) + 1];
        unsigned nz = __ballot_sync(0xffffffffu, (w0 | w1) != 0);
        if (lane == 0) g_is64 = (nz == 0u) ? 1 : 0;
    }
    int i = blockIdx.x * blockDim.x + threadIdx.x;
    if (i < N_NODES) g_deg[i] = 0;
    if (i < SCAN_NB) g_state[i] = 0ull;
}

// ---- 2. in-degree histogram over dst: 2 edges per thread, vector loads ----
__global__ void k_count(const void* __restrict__ ei) {
    int t = blockIdx.x * blockDim.x + threadIdx.x;
    if (t >= N_EDGES / 2) return;
    int d0, d1;
    if (g_is64) {
        longlong2 d2 = ((const longlong2*)ei)[(N_EDGES / 2) + t];
        d0 = clampN((int)d2.x); d1 = clampN((int)d2.y);
    } else {
        int2 d2 = ((const int2*)ei)[(N_EDGES / 2) + t];
        d0 = clampN(d2.x); d1 = clampN(d2.y);
    }
    atomicAdd(&g_deg[d0], 1);
    atomicAdd(&g_deg[d1], 1);
}

// ---- 3. single-kernel exclusive scan (decoupled lookback) + dinv ----
// All SCAN_NB=167 blocks are chip-resident concurrently => spin-wait is safe.
__global__ void __launch_bounds__(SCAN_B) k_scan() {
    __shared__ int sh[SCAN_B];
    __shared__ unsigned sbase;
    int bid = blockIdx.x;
    int tid = threadIdx.x;
    int i = bid * SCAN_B + tid;

    int v = (i < N_NODES) ? g_deg[i] : 0;
    if (i < N_NODES) g_dinv[i] = rsqrtf((float)(v + 1));   // fused dinv

    sh[tid] = v;
    __syncthreads();
    for (int d = 1; d < SCAN_B; d <<= 1) {
        int t = (tid >= d) ? sh[tid - d] : 0;
        __syncthreads();
        sh[tid] += t;
        __syncthreads();
    }
    int incl = sh[tid];
    int total = sh[SCAN_B - 1];

    // publish aggregate (block 0 publishes its prefix directly)
    if (tid == 0) {
        unsigned long long pk = ((bid == 0) ? (2ull << 32) : (1ull << 32))
                              | (unsigned long long)(unsigned)total;
        atomicExch(&g_state[bid], pk);
        if (bid == 0) sbase = 0u;
    }

    // warp 0: parallel lookback (32 predecessors per round)
    if (tid < 32 && bid > 0) {
        int lane = tid;
        unsigned excl = 0;
        int j = bid - 1;
        while (true) {
            int idx = j - lane;
            unsigned long long pk;
            if (idx >= 0) {
                do { pk = atomicAdd(&g_state[idx], 0ull); } while ((pk >> 32) == 0ull);
            } else {
                pk = (2ull << 32);   // virtual prefix 0 before block 0
            }
            unsigned flag = (unsigned)(pk >> 32);
            unsigned val  = (unsigned)pk;
            unsigned pm = __ballot_sync(0xffffffffu, flag == 2u);
            unsigned contrib;
            if (pm) {
                int fp = __ffs(pm) - 1;          // closest prefix (lane fp)
                contrib = (lane <= fp) ? val : 0; // aggregates before it + the prefix
            } else {
                contrib = val;                    // all aggregates; keep walking
            }
            #pragma unroll
            for (int d = 16; d >= 1; d >>= 1)
                contrib += __shfl_xor_sync(0xffffffffu, contrib, d);
            excl += contrib;
            if (pm) break;
            j -= 32;
        }
        if (lane == 0) {
            sbase = excl;
            atomicExch(&g_state[bid], (2ull << 32) | (unsigned long long)(excl + (unsigned)total));
        }
    }
    __syncthreads();

    if (i < N_NODES) g_off[i] = (int)sbase + (incl - v);   // exclusive
}

// ---- 4. project X(128) -> zs0(40), packed f32x2 FMA, TWO nodes per thread ----
// Weights staged in smem pair-transposed: sWf[(d*40)+c] = W[c][d]; one LDS.128
// (ulonglong2) yields 2 class-pairs for component d, shared by BOTH nodes
// => LDS issue per node halves (was the 80% L1 bottleneck).
__global__ void __launch_bounds__(256) k_project(const float4* __restrict__ x4,
                                                 const float*  __restrict__ Wf) {
    __shared__ float sWf[D_FEAT * N_CLASSES];   // 20 KB, [d][c]
    for (int i = threadIdx.x; i < D_FEAT * N_CLASSES; i += blockDim.x) {
        int d = i / N_CLASSES, c = i % N_CLASSES;
        sWf[i] = Wf[c * D_FEAT + d];
    }
    __syncthreads();

    int t = blockIdx.x * blockDim.x + threadIdx.x;
    if (t >= NHALF) return;
    int n0 = t;
    int n1 = t + NHALF;

    unsigned long long acc0[20], acc1[20];
    #pragma unroll
    for (int p = 0; p < 20; p++) { acc0[p] = 0ull; acc1[p] = 0ull; }

    const float4* h0 = x4 + (size_t)n0 * D4;
    const float4* h1 = x4 + (size_t)n1 * D4;
    #pragma unroll 1
    for (int k = 0; k < D4; k++) {
        float4 hv0 = h0[k];
        float4 hv1 = h1[k];
        float p0[4] = {hv0.x, hv0.y, hv0.z, hv0.w};
        float p1[4] = {hv1.x, hv1.y, hv1.z, hv1.w};
        #pragma unroll
        for (int comp = 0; comp < 4; comp++) {
            unsigned long long a0, a1;
            PACK_F32X2(a0, p0[comp], p0[comp]);
            PACK_F32X2(a1, p1[comp], p1[comp]);
            const ulonglong2* wrow =
                (const ulonglong2*)&sWf[(k * 4 + comp) * N_CLASSES];
            #pragma unroll
            for (int pp = 0; pp < 10; pp++) {
                ulonglong2 wv = wrow[pp];        // classes 4pp..4pp+3 of comp
                FMA_F32X2(acc0[2 * pp],     a0, wv.x);
                FMA_F32X2(acc1[2 * pp],     a1, wv.x);
                FMA_F32X2(acc0[2 * pp + 1], a0, wv.y);
                FMA_F32X2(acc1[2 * pp + 1], a1, wv.y);
            }
        }
    }

    float di0 = g_dinv[n0];
    float di1 = g_dinv[n1];
    float4* z0 = g_zs0 + (size_t)n0 * C4;
    float4* z1 = g_zs0 + (size_t)n1 * C4;
    #pragma unroll
    for (int q = 0; q < 10; q++) {
        float4 o;
        o.x = di0 * __uint_as_float((unsigned)acc0[2 * q]);
        o.y = di0 * __uint_as_float((unsigned)(acc0[2 * q] >> 32));
        o.z = di0 * __uint_as_float((unsigned)acc0[2 * q + 1]);
        o.w = di0 * __uint_as_float((unsigned)(acc0[2 * q + 1] >> 32));
        z0[q] = o;
        o.x = di1 * __uint_as_float((unsigned)acc1[2 * q]);
        o.y = di1 * __uint_as_float((unsigned)(acc1[2 * q] >> 32));
        o.z = di1 * __uint_as_float((unsigned)acc1[2 * q + 1]);
        o.w = di1 * __uint_as_float((unsigned)(acc1[2 * q + 1] >> 32));
        z1[q] = o;
    }
}

// ---- 5. scatter edges into CSR-by-dst: atomic-append on g_off directly ----
// Afterwards g_off[d] == END offset of d (shifted CSR: beg(d) = off[d-1], 0 for d=0).
__global__ void k_scatter(const void* __restrict__ ei) {
    int t = blockIdx.x * blockDim.x + threadIdx.x;
    if (t >= N_EDGES / 2) return;
    int s0, s1, d0, d1;
    if (g_is64) {
        longlong2 s2 = ((const longlong2*)ei)[t];
        longlong2 d2 = ((const longlong2*)ei)[(N_EDGES / 2) + t];
        s0 = clampN((int)s2.x); s1 = clampN((int)s2.y);
        d0 = clampN((int)d2.x); d1 = clampN((int)d2.y);
    } else {
        int2 s2 = ((const int2*)ei)[t];
        int2 d2 = ((const int2*)ei)[(N_EDGES / 2) + t];
        s0 = clampN(s2.x); s1 = clampN(s2.y);
        d0 = clampN(d2.x); d1 = clampN(d2.y);
    }
    g_srcs[atomicAdd(&g_off[d0], 1)] = s0;
    g_srcs[atomicAdd(&g_off[d1], 1)] = s1;
}

// ---- 6. propagation hop: TWO nodes per warp, float4 gathers, 2x MLP ----
// Half-warp (16 lanes) per node; lanes 0..9 hold the 10 float4 of the 160B row.
// Shifted CSR: beg = off[node-1] (0 for node 0), end = off[node].
// pass0:  zs1[i] = dinv[i]^2 * (sum zs0[s] + zs0[i])
// pass1:  logits = dinv[i] * (sum zs1[s] + zs1[i]) + b; out = log_softmax
__global__ void __launch_bounds__(256) k_hop(int pass,
                                             const float4* __restrict__ b4,
                                             float4*       __restrict__ out4) {
    const float4* zin = (pass == 0) ? (const float4*)g_zs0 : (const float4*)g_zs1;

    int warp = (blockIdx.x * blockDim.x + threadIdx.x) >> 5;
    int lane = threadIdx.x & 31;
    int half = lane >> 4;          // 0 or 1
    int hl   = lane & 15;          // lane within half
    int node = warp * 2 + half;    // N_NODES even; grid sized exactly
    bool act = hl < C4;            // lanes 0..9 active

    int beg = 0, end = 0;
    if (act) {
        beg = (node == 0) ? 0 : g_off[node - 1];
        end = g_off[node];
    }

    // self term
    float4 a = make_float4(0.f, 0.f, 0.f, 0.f);
    if (act) a = zin[(size_t)node * C4 + hl];

    // gather-sum over in-edges, 2x unrolled for MLP
    int p = beg;
    for (; p + 1 < end; p += 2) {
        int s0 = g_srcs[p];
        int s1 = g_srcs[p + 1];
        float4 u = zin[(size_t)s0 * C4 + hl];
        float4 v = zin[(size_t)s1 * C4 + hl];
        a.x += u.x + v.x;
        a.y += u.y + v.y;
        a.z += u.z + v.z;
        a.w += u.w + v.w;
    }
    if (p < end) {
        float4 u = zin[(size_t)g_srcs[p] * C4 + hl];
        a.x += u.x; a.y += u.y; a.z += u.z; a.w += u.w;
    }

    float di = act ? g_dinv[node] : 0.f;
    if (pass == 0) {
        if (act) {
            float di2 = di * di;
            float4 o;
            o.x = di2 * a.x; o.y = di2 * a.y; o.z = di2 * a.z; o.w = di2 * a.w;
            g_zs1[(size_t)node * C4 + hl] = o;
        }
    } else {
        float4 l = make_float4(-INFINITY, -INFINITY, -INFINITY, -INFINITY);
        if (act) {
            float4 bb = b4[hl];
            l.x = fmaf(di, a.x, bb.x);
            l.y = fmaf(di, a.y, bb.y);
            l.z = fmaf(di, a.z, bb.z);
            l.w = fmaf(di, a.w, bb.w);
        }

        float m = fmaxf(fmaxf(l.x, l.y), fmaxf(l.z, l.w));
        #pragma unroll
        for (int d = 8; d >= 1; d >>= 1)
            m = fmaxf(m, __shfl_xor_sync(0xffffffffu, m, d));

        float s = __expf(l.x - m) + __expf(l.y - m) +
                  __expf(l.z - m) + __expf(l.w - m);   // inactive: 4*exp(-inf)=0
        #pragma unroll
        for (int d = 8; d >= 1; d >>= 1)
            s += __shfl_xor_sync(0xffffffffu, s, d);

        float lse = m + logf(s);
        if (act) {
            float4 o;
            o.x = l.x - lse; o.y = l.y - lse; o.z = l.z - lse; o.w = l.w - lse;
            out4[(size_t)node * C4 + hl] = o;
        }
    }
}

extern "C" void kernel_launch(void* const* d_in, const int* in_sizes, int n_in,
                              void* d_out, int out_size) {
    const float4* x4  = (const float4*)d_in[0];
    const void*   ei  = d_in[1];
    const float*  Wf  = (const float*)d_in[2];
    const float4* b4  = (const float4*)d_in[3];
    float4*       out4 = (float4*)d_out;
    (void)in_sizes; (void)n_in; (void)out_size;

    const int TB = 256;
    int nblk_nodes = (N_NODES + TB - 1) / TB;
    int nblk_nhalf = (NHALF + TB - 1) / TB;
    int nblk_epair = (N_EDGES / 2 + TB - 1) / TB;

    k_zero<<<nblk_nodes, TB>>>((const int*)ei);   // + dtype probe + state reset
    k_count<<<nblk_epair, TB>>>(ei);
    k_scan<<<SCAN_NB, SCAN_B>>>();                // single-kernel scan + dinv
    k_project<<<nblk_nhalf, TB>>>(x4, Wf);        // 2 nodes per thread
    k_scatter<<<nblk_epair, TB>>>(ei);

    // 2 hops: two nodes per warp => N_NODES/2 warps
    int nblk_hop = (N_NODES / 2) * 32 / TB;       // 10625 blocks exactly
    k_hop<<<nblk_hop, TB>>>(0, b4, out4);
    k_hop<<<nblk_hop, TB>>>(1, b4, out4);
}